// round 12
// baseline (speedup 1.0000x reference)
#include <cuda_runtime.h>
#include <cstdint>

#define M_TOTAL 32768
#define E_DIM 2048
#define L_DIM 64
#define H_DIM 128
#define S_LEN 4096
#define NCHUNK 4        // qb-blocks per chunk = 64/NCHUNK = 16

// Scratch (device globals: allocation-free rule)
__device__ float g_q[(size_t)M_TOTAL * H_DIM];
__device__ float g_k[(size_t)M_TOTAL * H_DIM];
__device__ float g_v[(size_t)M_TOTAL * H_DIM];

// Pre-rounded (tf32-rna) weights, same layouts as inputs:
#define WR_DKV 0
#define WR_Q   (2048 * 64)
#define WR_K   (WR_Q + 2048 * 128)
#define WR_V   (WR_K + 64 * 128)
#define WR_TOT (WR_V + 64 * 128)
__device__ float g_wr[WR_TOT];

// ---------------- tf32 / async helpers ----------------

__device__ __forceinline__ void mma_tf32(float* d, const uint32_t* a, const uint32_t* b) {
    asm volatile(
        "mma.sync.aligned.m16n8k8.row.col.f32.tf32.tf32.f32 "
        "{%0,%1,%2,%3}, {%4,%5,%6,%7}, {%8,%9}, {%0,%1,%2,%3};\n"
        : "+f"(d[0]), "+f"(d[1]), "+f"(d[2]), "+f"(d[3])
        : "r"(a[0]), "r"(a[1]), "r"(a[2]), "r"(a[3]), "r"(b[0]), "r"(b[1]));
}

__device__ __forceinline__ uint32_t to_tf32(float x) {
    uint32_t h;
    asm("cvt.rna.tf32.f32 %0, %1;" : "=r"(h) : "f"(x));
    return h;
}

__device__ __forceinline__ void cp16(void* dst, const void* src) {
    uint32_t d = (uint32_t)__cvta_generic_to_shared(dst);
    asm volatile("cp.async.cg.shared.global [%0], [%1], 16;\n" :: "r"(d), "l"(src));
}
#define CP_COMMIT asm volatile("cp.async.commit_group;\n")
#define CP_WAIT0  asm volatile("cp.async.wait_group 0;\n")
#define CP_WAIT1  asm volatile("cp.async.wait_group 1;\n")
#define CP_WAIT2  asm volatile("cp.async.wait_group 2;\n")

// k scale folded into the fused epilogue: 1/sqrt(128) * log2(e)
#define KSCALE_C (0.08838834764831845f * 1.4426950408889634f)

// ---------------- weight pre-rounding (once per call, ~5us) ----------------

__global__ void prep_w(const float* __restrict__ w_dkv, const float* __restrict__ w_q,
                       const float* __restrict__ w_k, const float* __restrict__ w_v) {
    int i = blockIdx.x * 256 + threadIdx.x;
    float v;
    if (i < WR_Q)       v = w_dkv[i];
    else if (i < WR_K)  v = w_q[i - WR_Q];
    else if (i < WR_V)  v = w_k[i - WR_K];
    else                v = w_v[i - WR_V];
    g_wr[i] = __uint_as_float(to_tf32(v));
}

// ---------------- fused GEMM1 + k/v decompress (chunked by qb range) ----------------
// Chunk c covers, for every batch, q-blocks [16c, 16c+16) (rows 1024c..1024c+1023).
// Main loop: [latent(64) | q(128)] = x @ [w_dkv|w_q] (1xTF32, 3-stage cp.async).
// Epilogue: k = latent@w_k (KSCALE, rna), v = latent@w_v (rna), in-CTA.

constexpr int G_BN = 192;
constexpr int G_KT = 32;
constexpr int G_ASTR = 36;
constexpr int G_BSTR = G_BN + 8;              // 200
constexpr int G_ASZ = 64 * G_ASTR;            // 2304
constexpr int G_BSZ = G_KT * G_BSTR;          // 6400
constexpr int G_BUF = G_ASZ + G_BSZ;          // 8704 floats
constexpr int G_SMEM = 3 * G_BUF * 4;         // 104448 bytes
constexpr int WSTR = 264;
constexpr int EP_WS = 0;
constexpr int EP_LS = 64 * WSTR;
constexpr int LSTR = 68;
static_assert(EP_LS + 64 * LSTR <= 3 * G_BUF, "epilogue overlay fits");

__global__ void __launch_bounds__(256, 2) gemm1_fused(
    const float* __restrict__ A,
    const float* __restrict__ wr,
    float* __restrict__ latent, float* __restrict__ qout,
    float* __restrict__ kout, float* __restrict__ vout,
    int chunk)
{
    extern __shared__ float sh[];

    const int tid = threadIdx.x;
    const int warp = tid >> 5, lane = tid & 31;
    const int wm = warp >> 2;
    const int wn = warp & 3;
    const int lr = lane >> 2, lc = lane & 3;
    const int bx = blockIdx.x;                    // 0..127
    const int m0 = (bx >> 4) * S_LEN + (chunk * 16 + (bx & 15)) * 64;

    const int arow = tid >> 2;
    const int ac4 = (tid & 3) * 4;

    const float* B1 = wr + WR_DKV;
    const float* B2 = wr + WR_Q;

    float acc[2][6][4];
#pragma unroll
    for (int mt = 0; mt < 2; mt++)
#pragma unroll
        for (int nt = 0; nt < 6; nt++)
#pragma unroll
            for (int j = 0; j < 4; j++) acc[mt][nt][j] = 0.f;

    const int nk = E_DIM / G_KT;

    auto stage = [&](int kt) {
        float* As = sh + (kt % 3) * G_BUF;
        float* Bs = As + G_ASZ;
        int kb = kt * G_KT;
        cp16(&As[arow * G_ASTR + ac4],      A + (size_t)(m0 + arow) * E_DIM + kb + ac4);
        cp16(&As[arow * G_ASTR + ac4 + 16], A + (size_t)(m0 + arow) * E_DIM + kb + ac4 + 16);
        constexpr int NB = (G_KT * G_BN / 4) / 256;
#pragma unroll
        for (int it = 0; it < NB; it++) {
            int i = it * 256 + tid;
            int brow = i / (G_BN / 4);
            int bc4 = (i % (G_BN / 4)) * 4;
            const float* src = (bc4 < 64) ? (B1 + (size_t)(kb + brow) * L_DIM + bc4)
                                          : (B2 + (size_t)(kb + brow) * H_DIM + (bc4 - 64));
            cp16(&Bs[brow * G_BSTR + bc4], src);
        }
        CP_COMMIT;
    };

    stage(0);
    stage(1);

    for (int kt = 0; kt < nk; kt++) {
        if (kt + 2 < nk) { stage(kt + 2); CP_WAIT2; }
        else if (kt + 1 < nk) CP_WAIT1;
        else CP_WAIT0;
        __syncthreads();

        const float* As = sh + (kt % 3) * G_BUF;
        const float* Bs = As + G_ASZ;

#pragma unroll
        for (int ks = 0; ks < 4; ks++) {
            uint32_t ah[2][4];
#pragma unroll
            for (int mt = 0; mt < 2; mt++) {
                int rb = wm * 32 + mt * 16;
                ah[mt][0] = to_tf32(As[(rb + lr) * G_ASTR + ks * 8 + lc]);
                ah[mt][1] = to_tf32(As[(rb + lr + 8) * G_ASTR + ks * 8 + lc]);
                ah[mt][2] = to_tf32(As[(rb + lr) * G_ASTR + ks * 8 + lc + 4]);
                ah[mt][3] = to_tf32(As[(rb + lr + 8) * G_ASTR + ks * 8 + lc + 4]);
            }
#pragma unroll
            for (int nt = 0; nt < 6; nt++) {
                int c0 = wn * 48 + nt * 8 + lr;
                uint32_t bh[2];
                bh[0] = __float_as_uint(Bs[(ks * 8 + lc) * G_BSTR + c0]);
                bh[1] = __float_as_uint(Bs[(ks * 8 + lc + 4) * G_BSTR + c0]);
#pragma unroll
                for (int mt = 0; mt < 2; mt++)
                    mma_tf32(acc[mt][nt], ah[mt], bh);
            }
        }
        __syncthreads();
    }

    // ---- epilogue: stage w_k|w_v into dead pipeline smem (overlapped) ----
    {
        float* Ws = sh + EP_WS;
#pragma unroll
        for (int it = 0; it < 16; it++) {
            int i = it * 256 + tid;
            int row = i >> 6;
            int c4 = (i & 63) * 4;
            const float* src = (c4 < 128) ? (wr + WR_K + (size_t)row * H_DIM + c4)
                                          : (wr + WR_V + (size_t)row * H_DIM + (c4 - 128));
            cp16(&Ws[row * WSTR + c4], src);
        }
        CP_COMMIT;
    }

    // ---- store latent (d_out + smem) and q (gmem) ----
    {
        float* Ls = sh + EP_LS;
#pragma unroll
        for (int mt = 0; mt < 2; mt++) {
            int rloc = wm * 32 + mt * 16 + lr;
            int r0 = m0 + rloc;
#pragma unroll
            for (int nt = 0; nt < 6; nt++) {
                int gc = wn * 48 + nt * 8 + lc * 2;
                float2 v01 = make_float2(acc[mt][nt][0], acc[mt][nt][1]);
                float2 v23 = make_float2(acc[mt][nt][2], acc[mt][nt][3]);
                if (gc < 64) {
                    *(float2*)(latent + (size_t)r0 * L_DIM + gc)       = v01;
                    *(float2*)(latent + (size_t)(r0 + 8) * L_DIM + gc) = v23;
                    *(float2*)&Ls[rloc * LSTR + gc]       = v01;
                    *(float2*)&Ls[(rloc + 8) * LSTR + gc] = v23;
                } else {
                    *(float2*)(qout + (size_t)r0 * H_DIM + gc - 64)       = v01;
                    *(float2*)(qout + (size_t)(r0 + 8) * H_DIM + gc - 64) = v23;
                }
            }
        }
    }
    CP_WAIT0;
    __syncthreads();

    // ---- k|v = latent @ [w_k|w_v] ----
    {
        const float* Ws = sh + EP_WS;
        const float* Ls = sh + EP_LS;
        float acc2[2][8][4];
#pragma unroll
        for (int mt = 0; mt < 2; mt++)
#pragma unroll
            for (int nt = 0; nt < 8; nt++)
#pragma unroll
                for (int j = 0; j < 4; j++) acc2[mt][nt][j] = 0.f;

#pragma unroll
        for (int ks = 0; ks < 8; ks++) {
            uint32_t ah[2][4];
#pragma unroll
            for (int mt = 0; mt < 2; mt++) {
                int rb = wm * 32 + mt * 16;
                ah[mt][0] = to_tf32(Ls[(rb + lr) * LSTR + ks * 8 + lc]);
                ah[mt][1] = to_tf32(Ls[(rb + lr + 8) * LSTR + ks * 8 + lc]);
                ah[mt][2] = to_tf32(Ls[(rb + lr) * LSTR + ks * 8 + lc + 4]);
                ah[mt][3] = to_tf32(Ls[(rb + lr + 8) * LSTR + ks * 8 + lc + 4]);
            }
#pragma unroll
            for (int nt = 0; nt < 8; nt++) {
                int c0 = wn * 64 + nt * 8 + lr;
                uint32_t bh[2];
                bh[0] = __float_as_uint(Ws[(ks * 8 + lc) * WSTR + c0]);
                bh[1] = __float_as_uint(Ws[(ks * 8 + lc + 4) * WSTR + c0]);
#pragma unroll
                for (int mt = 0; mt < 2; mt++)
                    mma_tf32(acc2[mt][nt], ah[mt], bh);
            }
        }

#pragma unroll
        for (int mt = 0; mt < 2; mt++) {
            int r0 = m0 + wm * 32 + mt * 16 + lr;
#pragma unroll
            for (int nt = 0; nt < 8; nt++) {
                int gc = wn * 64 + nt * 8 + lc * 2;
                float* dst;
                int col;
                float cs;
                if (gc < 128) { dst = kout; col = gc;       cs = KSCALE_C; }
                else          { dst = vout; col = gc - 128; cs = 1.f; }
                float o0 = __uint_as_float(to_tf32(acc2[mt][nt][0] * cs));
                float o1 = __uint_as_float(to_tf32(acc2[mt][nt][1] * cs));
                float o2 = __uint_as_float(to_tf32(acc2[mt][nt][2] * cs));
                float o3 = __uint_as_float(to_tf32(acc2[mt][nt][3] * cs));
                *(float2*)(dst + (size_t)r0 * H_DIM + col)       = make_float2(o0, o1);
                *(float2*)(dst + (size_t)(r0 + 8) * H_DIM + col) = make_float2(o2, o3);
            }
        }
    }
}

// ---------------- Flash attention (causal), chunked by qb range ----------------
// Chunk c: qb in [16c, 16c+16) x 8 batches = 128 CTAs, longest-first.
// Geometry/numerics identical to R9 (proven 245us kernel).

constexpr int AKS = 132;
constexpr int AVS = 136;
constexpr int APS = 68;
constexpr int VOFF = 64 * AKS;
constexpr int XOFF = VOFF + 64 * AVS;
constexpr int QOFF = XOFF + 128;
constexpr int ATTN_SMEM_BYTES = (QOFF + 64 * 132) * 4;   // 102912

__global__ void __launch_bounds__(128, 2) attn_kernel(
    const float* __restrict__ q, const float* __restrict__ k,
    const float* __restrict__ v, float* __restrict__ out, int chunk)
{
    extern __shared__ float sm[];
    float* Ks = sm;
    float* Vs = sm + VOFF;
    float* Xb = sm + XOFF;
    float* Qs = sm + QOFF;

    const int idx = blockIdx.x;                     // 0..127
    const int b = idx & 7;
    const int qb = chunk * 16 + 15 - (idx >> 3);    // longest-first within chunk
    const int tid = threadIdx.x;
    const int warp = tid >> 5, lane = tid & 31;
    const int lr = lane >> 2, lc = lane & 3;
    const int wm = warp >> 1;
    const int wn = warp & 1;

    const float* qB = q + (size_t)b * S_LEN * H_DIM;
    const float* kB = k + (size_t)b * S_LEN * H_DIM;
    const float* vB = v + (size_t)b * S_LEN * H_DIM;

    const int row64 = tid >> 5;
    const int c4 = (tid & 31) * 4;

#pragma unroll
    for (int rnd = 0; rnd < 16; rnd++) {
        int row = row64 + rnd * 4;
        cp16(&Qs[row * 132 + c4], qB + (size_t)(qb * 64 + row) * H_DIM + c4);
    }
    CP_COMMIT;

    const int qrow0 = qb * 64 + wm * 32 + lr;
    uint32_t qr[64];
#pragma unroll
    for (int ks = 0; ks < 16; ks++) {
        int c = ks * 8 + lc;
        qr[ks * 4 + 0] = to_tf32(qB[(size_t)qrow0 * H_DIM + c]);
        qr[ks * 4 + 1] = to_tf32(qB[(size_t)(qrow0 + 8) * H_DIM + c]);
        qr[ks * 4 + 2] = to_tf32(qB[(size_t)qrow0 * H_DIM + c + 4]);
        qr[ks * 4 + 3] = to_tf32(qB[(size_t)(qrow0 + 8) * H_DIM + c + 4]);
    }

    float acc[2][8][4];
#pragma unroll
    for (int mt = 0; mt < 2; mt++)
#pragma unroll
        for (int nt = 0; nt < 8; nt++)
#pragma unroll
            for (int j = 0; j < 4; j++) acc[mt][nt][j] = 0.f;
    float mrow[2][2] = {{-INFINITY, -INFINITY}, {-INFINITY, -INFINITY}};
    float lrow[2][2] = {{0.f, 0.f}, {0.f, 0.f}};

    for (int kv = 0; kv <= qb; kv++) {
        __syncthreads();

#pragma unroll
        for (int rnd = 0; rnd < 16; rnd++) {
            int row = row64 + rnd * 4;
            cp16(&Ks[row * AKS + c4], kB + (size_t)(kv * 64 + row) * H_DIM + c4);
            cp16(&Vs[row * AVS + c4], vB + (size_t)(kv * 64 + row) * H_DIM + c4);
        }
        CP_COMMIT;
        CP_WAIT0;
        __syncthreads();

        float sc[2][4][4];
#pragma unroll
        for (int mt = 0; mt < 2; mt++)
#pragma unroll
            for (int nt = 0; nt < 4; nt++)
#pragma unroll
                for (int j = 0; j < 4; j++) sc[mt][nt][j] = 0.f;

        const int q1row = wm * 32 + 16 + lr;
#pragma unroll
        for (int ks = 0; ks < 16; ks++) {
            uint32_t q1[4];
            q1[0] = to_tf32(Qs[q1row * 132 + ks * 8 + lc]);
            q1[1] = to_tf32(Qs[(q1row + 8) * 132 + ks * 8 + lc]);
            q1[2] = to_tf32(Qs[q1row * 132 + ks * 8 + lc + 4]);
            q1[3] = to_tf32(Qs[(q1row + 8) * 132 + ks * 8 + lc + 4]);
#pragma unroll
            for (int nt = 0; nt < 4; nt++) {
                int kr = wn * 32 + nt * 8 + lr;
                uint32_t bh[2];
                bh[0] = __float_as_uint(Ks[kr * AKS + ks * 8 + lc]);
                bh[1] = __float_as_uint(Ks[kr * AKS + ks * 8 + lc + 4]);
                mma_tf32(sc[0][nt], &qr[ks * 4], bh);
                mma_tf32(sc[1][nt], q1, bh);
            }
        }

        if (kv == qb) {
#pragma unroll
            for (int mt = 0; mt < 2; mt++)
#pragma unroll
                for (int nt = 0; nt < 4; nt++)
#pragma unroll
                    for (int j = 0; j < 4; j++) {
                        int col = wn * 32 + nt * 8 + lc * 2 + (j & 1);
                        int row = wm * 32 + mt * 16 + lr + (j >> 1) * 8;
                        if (col > row) sc[mt][nt][j] = -INFINITY;
                    }
        }

        float mnew[2][2] = {{-INFINITY, -INFINITY}, {-INFINITY, -INFINITY}};
#pragma unroll
        for (int mt = 0; mt < 2; mt++)
#pragma unroll
            for (int nt = 0; nt < 4; nt++)
#pragma unroll
                for (int j = 0; j < 4; j++)
                    mnew[mt][j >> 1] = fmaxf(mnew[mt][j >> 1], sc[mt][nt][j]);
#pragma unroll
        for (int off = 1; off < 4; off <<= 1)
#pragma unroll
            for (int mt = 0; mt < 2; mt++) {
                mnew[mt][0] = fmaxf(mnew[mt][0], __shfl_xor_sync(0xffffffffu, mnew[mt][0], off));
                mnew[mt][1] = fmaxf(mnew[mt][1], __shfl_xor_sync(0xffffffffu, mnew[mt][1], off));
            }
        if (lc == 0) {
#pragma unroll
            for (int mt = 0; mt < 2; mt++)
#pragma unroll
                for (int h = 0; h < 2; h++)
                    Xb[((wm * 2 + wn) * 4 + mt * 2 + h) * 8 + lr] = mnew[mt][h];
        }
        __syncthreads();

        float alpha[2][2];
#pragma unroll
        for (int mt = 0; mt < 2; mt++)
#pragma unroll
            for (int h = 0; h < 2; h++) {
                float mo = Xb[((wm * 2 + (1 - wn)) * 4 + mt * 2 + h) * 8 + lr];
                float mt_ = fmaxf(fmaxf(mrow[mt][h], mnew[mt][h]), mo);
                alpha[mt][h] = exp2f(mrow[mt][h] - mt_);
                mrow[mt][h] = mt_;
            }

        float rs[2][2] = {{0.f, 0.f}, {0.f, 0.f}};
#pragma unroll
        for (int mt = 0; mt < 2; mt++)
#pragma unroll
            for (int nt = 0; nt < 4; nt++)
#pragma unroll
                for (int j = 0; j < 4; j++) {
                    float p = exp2f(sc[mt][nt][j] - mrow[mt][j >> 1]);
                    sc[mt][nt][j] = p;
                    rs[mt][j >> 1] += p;
                }
#pragma unroll
        for (int off = 1; off < 4; off <<= 1)
#pragma unroll
            for (int mt = 0; mt < 2; mt++) {
                rs[mt][0] += __shfl_xor_sync(0xffffffffu, rs[mt][0], off);
                rs[mt][1] += __shfl_xor_sync(0xffffffffu, rs[mt][1], off);
            }

#pragma unroll
        for (int mt = 0; mt < 2; mt++)
#pragma unroll
            for (int nt = 0; nt < 4; nt++)
#pragma unroll
                for (int j = 0; j < 4; j++) {
                    int row = wm * 32 + mt * 16 + lr + (j >> 1) * 8;
                    int col = wn * 32 + nt * 8 + lc * 2 + (j & 1);
                    Ks[row * APS + col] = __uint_as_float(to_tf32(sc[mt][nt][j]));
                }
        if (lc == 0) {
#pragma unroll
            for (int mt = 0; mt < 2; mt++)
#pragma unroll
                for (int h = 0; h < 2; h++)
                    Xb[64 + ((wm * 2 + wn) * 4 + mt * 2 + h) * 8 + lr] = rs[mt][h];
        }
        __syncthreads();

#pragma unroll
        for (int mt = 0; mt < 2; mt++)
#pragma unroll
            for (int h = 0; h < 2; h++) {
                float ro = Xb[64 + ((wm * 2 + (1 - wn)) * 4 + mt * 2 + h) * 8 + lr];
                lrow[mt][h] = lrow[mt][h] * alpha[mt][h] + rs[mt][h] + ro;
            }

#pragma unroll
        for (int mt = 0; mt < 2; mt++)
#pragma unroll
            for (int nt = 0; nt < 8; nt++) {
                acc[mt][nt][0] *= alpha[mt][0]; acc[mt][nt][1] *= alpha[mt][0];
                acc[mt][nt][2] *= alpha[mt][1]; acc[mt][nt][3] *= alpha[mt][1];
            }

#pragma unroll
        for (int ks2 = 0; ks2 < 8; ks2++) {
            uint32_t pa[2][4];
#pragma unroll
            for (int mt = 0; mt < 2; mt++) {
                int base = wm * 32 + mt * 16;
                pa[mt][0] = __float_as_uint(Ks[(base + lr) * APS + ks2 * 8 + lc]);
                pa[mt][1] = __float_as_uint(Ks[(base + lr + 8) * APS + ks2 * 8 + lc]);
                pa[mt][2] = __float_as_uint(Ks[(base + lr) * APS + ks2 * 8 + lc + 4]);
                pa[mt][3] = __float_as_uint(Ks[(base + lr + 8) * APS + ks2 * 8 + lc + 4]);
            }
#pragma unroll
            for (int nt2 = 0; nt2 < 8; nt2++) {
                int vc = wn * 64 + nt2 * 8 + lr;
                uint32_t vb[2];
                vb[0] = __float_as_uint(Vs[(ks2 * 8 + lc) * AVS + vc]);
                vb[1] = __float_as_uint(Vs[(ks2 * 8 + lc + 4) * AVS + vc]);
                mma_tf32(acc[0][nt2], pa[0], vb);
                mma_tf32(acc[1][nt2], pa[1], vb);
            }
        }
    }

#pragma unroll
    for (int mt = 0; mt < 2; mt++) {
        float inv0 = 1.f / lrow[mt][0];
        float inv1 = 1.f / lrow[mt][1];
        size_t rowg = (size_t)b * S_LEN + qb * 64 + wm * 32 + mt * 16 + lr;
#pragma unroll
        for (int nt2 = 0; nt2 < 8; nt2++) {
            int col = wn * 64 + nt2 * 8 + lc * 2;
            *(float2*)(out + rowg * H_DIM + col) =
                make_float2(acc[mt][nt2][0] * inv0, acc[mt][nt2][1] * inv0);
            *(float2*)(out + (rowg + 8) * H_DIM + col) =
                make_float2(acc[mt][nt2][2] * inv1, acc[mt][nt2][3] * inv1);
        }
    }
}

// ---------------- launch: chunked producer/consumer pipeline ----------------

extern "C" void kernel_launch(void* const* d_in, const int* in_sizes, int n_in,
                              void* d_out, int out_size) {
    const float* x     = (const float*)d_in[0];
    const float* w_dkv = (const float*)d_in[1];
    const float* w_k   = (const float*)d_in[2];
    const float* w_v   = (const float*)d_in[3];
    const float* w_q   = (const float*)d_in[4];

    float* out = (float*)d_out;                          // [B,S,HEAD]
    float* latent = out + (size_t)M_TOTAL * H_DIM;       // [B,S,LATENT]

    float *qp, *kp, *vp, *wr;
    cudaGetSymbolAddress((void**)&qp, g_q);
    cudaGetSymbolAddress((void**)&kp, g_k);
    cudaGetSymbolAddress((void**)&vp, g_v);
    cudaGetSymbolAddress((void**)&wr, g_wr);

    static bool inited = false;
    static cudaStream_t s_attn[2];
    static cudaEvent_t ev_g[NCHUNK], ev_a[NCHUNK];
    if (!inited) {
        cudaFuncSetAttribute(gemm1_fused,
                             cudaFuncAttributeMaxDynamicSharedMemorySize, G_SMEM);
        cudaFuncSetAttribute(attn_kernel,
                             cudaFuncAttributeMaxDynamicSharedMemorySize, ATTN_SMEM_BYTES);
        cudaStreamCreateWithFlags(&s_attn[0], cudaStreamNonBlocking);
        cudaStreamCreateWithFlags(&s_attn[1], cudaStreamNonBlocking);
        for (int c = 0; c < NCHUNK; c++) {
            cudaEventCreateWithFlags(&ev_g[c], cudaEventDisableTiming);
            cudaEventCreateWithFlags(&ev_a[c], cudaEventDisableTiming);
        }
        inited = true;
    }

    // 0) pre-round all weights (on main/capture stream)
    prep_w<<<WR_TOT / 256, 256>>>(w_dkv, w_q, w_k, w_v);

    // 1) pipeline: gemm chunk c (ascending kv rows) -> event -> attn chunk c
    //    (attn chunk c needs k/v rows <= 1024*(c+1): produced by chunks 0..c)
    for (int c = 0; c < NCHUNK; c++) {
        gemm1_fused<<<128, 256, G_SMEM>>>(x, wr, latent, qp, kp, vp, c);
        cudaEventRecord(ev_g[c], 0);
        cudaStream_t sa = s_attn[c & 1];
        cudaStreamWaitEvent(sa, ev_g[c], 0);
        attn_kernel<<<128, 128, ATTN_SMEM_BYTES, sa>>>(qp, kp, vp, out, c);
        cudaEventRecord(ev_a[c], sa);
    }

    // 2) join all attention chunks back to the main/capture stream
    for (int c = 0; c < NCHUNK; c++)
        cudaStreamWaitEvent(0, ev_a[c], 0);
}

// round 14
// speedup vs baseline: 1.3941x; 1.3941x over previous
#include <cuda_runtime.h>
#include <cstdint>

#define M_TOTAL 32768
#define E_DIM 2048
#define L_DIM 64
#define H_DIM 128
#define S_LEN 4096

// Scratch (device globals: allocation-free rule)
__device__ float g_q[(size_t)M_TOTAL * H_DIM];
__device__ float g_k[(size_t)M_TOTAL * H_DIM];
__device__ float g_v[(size_t)M_TOTAL * H_DIM];

// Pre-rounded (tf32-rna) weights, same layouts as inputs:
#define WR_DKV 0
#define WR_Q   (2048 * 64)
#define WR_K   (WR_Q + 2048 * 128)
#define WR_V   (WR_K + 64 * 128)
#define WR_TOT (WR_V + 64 * 128)
__device__ float g_wr[WR_TOT];

// ---------------- tf32 / async helpers ----------------

__device__ __forceinline__ void mma_tf32(float* d, const uint32_t* a, const uint32_t* b) {
    asm volatile(
        "mma.sync.aligned.m16n8k8.row.col.f32.tf32.tf32.f32 "
        "{%0,%1,%2,%3}, {%4,%5,%6,%7}, {%8,%9}, {%0,%1,%2,%3};\n"
        : "+f"(d[0]), "+f"(d[1]), "+f"(d[2]), "+f"(d[3])
        : "r"(a[0]), "r"(a[1]), "r"(a[2]), "r"(a[3]), "r"(b[0]), "r"(b[1]));
}

__device__ __forceinline__ uint32_t to_tf32(float x) {
    uint32_t h;
    asm("cvt.rna.tf32.f32 %0, %1;" : "=r"(h) : "f"(x));
    return h;
}

__device__ __forceinline__ void cp16(void* dst, const void* src) {
    uint32_t d = (uint32_t)__cvta_generic_to_shared(dst);
    asm volatile("cp.async.cg.shared.global [%0], [%1], 16;\n" :: "r"(d), "l"(src));
}
#define CP_COMMIT asm volatile("cp.async.commit_group;\n")
#define CP_WAIT0  asm volatile("cp.async.wait_group 0;\n")
#define CP_WAIT1  asm volatile("cp.async.wait_group 1;\n")
#define CP_WAIT2  asm volatile("cp.async.wait_group 2;\n")

// k scale folded into the fused epilogue: 1/sqrt(128) * log2(e)
#define KSCALE_C (0.08838834764831845f * 1.4426950408889634f)

// ---------------- weight pre-rounding (once per call, ~5us) ----------------

__global__ void prep_w(const float* __restrict__ w_dkv, const float* __restrict__ w_q,
                       const float* __restrict__ w_k, const float* __restrict__ w_v) {
    int i = blockIdx.x * 256 + threadIdx.x;
    float v;
    if (i < WR_Q)       v = w_dkv[i];
    else if (i < WR_K)  v = w_q[i - WR_Q];
    else if (i < WR_V)  v = w_k[i - WR_K];
    else                v = w_v[i - WR_V];
    g_wr[i] = __uint_as_float(to_tf32(v));
}

// ---------------- fused GEMM1 + k/v decompress ----------------
// Main loop: [latent(64) | q(128)] = x[M,2048] @ [w_dkv|w_q] (1xTF32, 3-stage
// cp.async). Epilogue: latent kept in smem; k = latent@w_k (KSCALE, rna),
// v = latent@w_v (rna) computed in-CTA from pre-rounded weights staged into
// the dead pipeline buffers. BM=64, 256 threads = 8 warps 2(m) x 4(n).

constexpr int G_BN = 192;
constexpr int G_KT = 32;
constexpr int G_ASTR = 36;
constexpr int G_BSTR = G_BN + 8;              // 200
constexpr int G_ASZ = 64 * G_ASTR;            // 2304
constexpr int G_BSZ = G_KT * G_BSTR;          // 6400
constexpr int G_BUF = G_ASZ + G_BSZ;          // 8704 floats
constexpr int G_SMEM = 3 * G_BUF * 4;         // 104448 bytes
constexpr int WSTR = 264;
constexpr int EP_WS = 0;
constexpr int EP_LS = 64 * WSTR;
constexpr int LSTR = 68;
static_assert(EP_LS + 64 * LSTR <= 3 * G_BUF, "epilogue overlay fits");

__global__ void __launch_bounds__(256, 2) gemm1_fused(
    const float* __restrict__ A,
    const float* __restrict__ wr,
    float* __restrict__ latent, float* __restrict__ qout,
    float* __restrict__ kout, float* __restrict__ vout)
{
    extern __shared__ float sh[];

    const int tid = threadIdx.x;
    const int warp = tid >> 5, lane = tid & 31;
    const int wm = warp >> 2;
    const int wn = warp & 3;
    const int lr = lane >> 2, lc = lane & 3;
    const int m0 = blockIdx.x * 64;

    const int arow = tid >> 2;
    const int ac4 = (tid & 3) * 4;

    const float* B1 = wr + WR_DKV;
    const float* B2 = wr + WR_Q;

    float acc[2][6][4];
#pragma unroll
    for (int mt = 0; mt < 2; mt++)
#pragma unroll
        for (int nt = 0; nt < 6; nt++)
#pragma unroll
            for (int j = 0; j < 4; j++) acc[mt][nt][j] = 0.f;

    const int nk = E_DIM / G_KT;

    auto stage = [&](int kt) {
        float* As = sh + (kt % 3) * G_BUF;
        float* Bs = As + G_ASZ;
        int kb = kt * G_KT;
        cp16(&As[arow * G_ASTR + ac4],      A + (size_t)(m0 + arow) * E_DIM + kb + ac4);
        cp16(&As[arow * G_ASTR + ac4 + 16], A + (size_t)(m0 + arow) * E_DIM + kb + ac4 + 16);
        constexpr int NB = (G_KT * G_BN / 4) / 256;  // 6
#pragma unroll
        for (int it = 0; it < NB; it++) {
            int i = it * 256 + tid;
            int brow = i / (G_BN / 4);
            int bc4 = (i % (G_BN / 4)) * 4;
            const float* src = (bc4 < 64) ? (B1 + (size_t)(kb + brow) * L_DIM + bc4)
                                          : (B2 + (size_t)(kb + brow) * H_DIM + (bc4 - 64));
            cp16(&Bs[brow * G_BSTR + bc4], src);
        }
        CP_COMMIT;
    };

    stage(0);
    stage(1);

    for (int kt = 0; kt < nk; kt++) {
        if (kt + 2 < nk) { stage(kt + 2); CP_WAIT2; }
        else if (kt + 1 < nk) CP_WAIT1;
        else CP_WAIT0;
        __syncthreads();

        const float* As = sh + (kt % 3) * G_BUF;
        const float* Bs = As + G_ASZ;

#pragma unroll
        for (int ks = 0; ks < 4; ks++) {
            uint32_t ah[2][4];
#pragma unroll
            for (int mt = 0; mt < 2; mt++) {
                int rb = wm * 32 + mt * 16;
                ah[mt][0] = to_tf32(As[(rb + lr) * G_ASTR + ks * 8 + lc]);
                ah[mt][1] = to_tf32(As[(rb + lr + 8) * G_ASTR + ks * 8 + lc]);
                ah[mt][2] = to_tf32(As[(rb + lr) * G_ASTR + ks * 8 + lc + 4]);
                ah[mt][3] = to_tf32(As[(rb + lr + 8) * G_ASTR + ks * 8 + lc + 4]);
            }
#pragma unroll
            for (int nt = 0; nt < 6; nt++) {
                int c0 = wn * 48 + nt * 8 + lr;
                uint32_t bh[2];
                bh[0] = __float_as_uint(Bs[(ks * 8 + lc) * G_BSTR + c0]);
                bh[1] = __float_as_uint(Bs[(ks * 8 + lc + 4) * G_BSTR + c0]);
#pragma unroll
                for (int mt = 0; mt < 2; mt++)
                    mma_tf32(acc[mt][nt], ah[mt], bh);
            }
        }
        __syncthreads();
    }

    // ---- epilogue: stage w_k|w_v into dead pipeline smem (overlapped) ----
    {
        float* Ws = sh + EP_WS;
#pragma unroll
        for (int it = 0; it < 16; it++) {
            int i = it * 256 + tid;
            int row = i >> 6;
            int c4 = (i & 63) * 4;
            const float* src = (c4 < 128) ? (wr + WR_K + (size_t)row * H_DIM + c4)
                                          : (wr + WR_V + (size_t)row * H_DIM + (c4 - 128));
            cp16(&Ws[row * WSTR + c4], src);
        }
        CP_COMMIT;
    }

    // ---- store latent (d_out + smem) and q (gmem) ----
    {
        float* Ls = sh + EP_LS;
#pragma unroll
        for (int mt = 0; mt < 2; mt++) {
            int rloc = wm * 32 + mt * 16 + lr;
            int r0 = m0 + rloc;
#pragma unroll
            for (int nt = 0; nt < 6; nt++) {
                int gc = wn * 48 + nt * 8 + lc * 2;
                float2 v01 = make_float2(acc[mt][nt][0], acc[mt][nt][1]);
                float2 v23 = make_float2(acc[mt][nt][2], acc[mt][nt][3]);
                if (gc < 64) {
                    *(float2*)(latent + (size_t)r0 * L_DIM + gc)       = v01;
                    *(float2*)(latent + (size_t)(r0 + 8) * L_DIM + gc) = v23;
                    *(float2*)&Ls[rloc * LSTR + gc]       = v01;
                    *(float2*)&Ls[(rloc + 8) * LSTR + gc] = v23;
                } else {
                    *(float2*)(qout + (size_t)r0 * H_DIM + gc - 64)       = v01;
                    *(float2*)(qout + (size_t)(r0 + 8) * H_DIM + gc - 64) = v23;
                }
            }
        }
    }
    CP_WAIT0;
    __syncthreads();

    // ---- k|v = latent @ [w_k|w_v] : warp = 32 rows (2mt) x 64 cols (8nt) ----
    {
        const float* Ws = sh + EP_WS;
        const float* Ls = sh + EP_LS;
        float acc2[2][8][4];
#pragma unroll
        for (int mt = 0; mt < 2; mt++)
#pragma unroll
            for (int nt = 0; nt < 8; nt++)
#pragma unroll
                for (int j = 0; j < 4; j++) acc2[mt][nt][j] = 0.f;

#pragma unroll
        for (int ks = 0; ks < 8; ks++) {
            uint32_t ah[2][4];
#pragma unroll
            for (int mt = 0; mt < 2; mt++) {
                int rb = wm * 32 + mt * 16;
                ah[mt][0] = to_tf32(Ls[(rb + lr) * LSTR + ks * 8 + lc]);
                ah[mt][1] = to_tf32(Ls[(rb + lr + 8) * LSTR + ks * 8 + lc]);
                ah[mt][2] = to_tf32(Ls[(rb + lr) * LSTR + ks * 8 + lc + 4]);
                ah[mt][3] = to_tf32(Ls[(rb + lr + 8) * LSTR + ks * 8 + lc + 4]);
            }
#pragma unroll
            for (int nt = 0; nt < 8; nt++) {
                int c0 = wn * 64 + nt * 8 + lr;
                uint32_t bh[2];
                bh[0] = __float_as_uint(Ws[(ks * 8 + lc) * WSTR + c0]);
                bh[1] = __float_as_uint(Ws[(ks * 8 + lc + 4) * WSTR + c0]);
#pragma unroll
                for (int mt = 0; mt < 2; mt++)
                    mma_tf32(acc2[mt][nt], ah[mt], bh);
            }
        }

#pragma unroll
        for (int mt = 0; mt < 2; mt++) {
            int r0 = m0 + wm * 32 + mt * 16 + lr;
#pragma unroll
            for (int nt = 0; nt < 8; nt++) {
                int gc = wn * 64 + nt * 8 + lc * 2;
                float* dst;
                int col;
                float cs;
                if (gc < 128) { dst = kout; col = gc;       cs = KSCALE_C; }
                else          { dst = vout; col = gc - 128; cs = 1.f; }
                float o0 = __uint_as_float(to_tf32(acc2[mt][nt][0] * cs));
                float o1 = __uint_as_float(to_tf32(acc2[mt][nt][1] * cs));
                float o2 = __uint_as_float(to_tf32(acc2[mt][nt][2] * cs));
                float o3 = __uint_as_float(to_tf32(acc2[mt][nt][3] * cs));
                *(float2*)(dst + (size_t)r0 * H_DIM + col)       = make_float2(o0, o1);
                *(float2*)(dst + (size_t)(r0 + 8) * H_DIM + col) = make_float2(o2, o3);
            }
        }
    }
}

// ---------------- Flash attention (causal), R9 geometry + pre-rounded Q tile ----
// BLOCK_M=64, 4 warps = (wm: 32-row half) x (wn: 32-kv half QK / 64-head half PV).
// Q staged once, rna-rounded IN PLACE (one pass, no extra barrier) -> QK inner
// loop has zero cvt on q. q mt0 fragments in regs (loaded from rounded Qs),
// mt1 from Qs. P aliases Ks. k pre-scaled by 1/sqrt(128)*log2e; exp2 softmax.

constexpr int AKS = 132;
constexpr int AVS = 136;
constexpr int APS = 68;
constexpr int VOFF = 64 * AKS;
constexpr int XOFF = VOFF + 64 * AVS;
constexpr int QOFF = XOFF + 128;
constexpr int ATTN_SMEM_BYTES = (QOFF + 64 * 132) * 4;   // 102912

__global__ void __launch_bounds__(128, 2) attn_kernel(
    const float* __restrict__ q, const float* __restrict__ k,
    const float* __restrict__ v, float* __restrict__ out)
{
    extern __shared__ float sm[];
    float* Ks = sm;
    float* Vs = sm + VOFF;
    float* Xb = sm + XOFF;
    float* Qs = sm + QOFF;

    const int idx = blockIdx.x;
    const int b = idx & 7;
    const int qb = 63 - (idx >> 3);         // longest first
    const int tid = threadIdx.x;
    const int warp = tid >> 5, lane = tid & 31;
    const int lr = lane >> 2, lc = lane & 3;
    const int wm = warp >> 1;
    const int wn = warp & 1;

    const float* qB = q + (size_t)b * S_LEN * H_DIM;
    const float* kB = k + (size_t)b * S_LEN * H_DIM;
    const float* vB = v + (size_t)b * S_LEN * H_DIM;

    const int row64 = tid >> 5;
    const int c4 = (tid & 31) * 4;

    // Stage Q tile (64 x 128) once
#pragma unroll
    for (int rnd = 0; rnd < 16; rnd++) {
        int row = row64 + rnd * 4;
        cp16(&Qs[row * 132 + c4], qB + (size_t)(qb * 64 + row) * H_DIM + c4);
    }
    CP_COMMIT;

    uint32_t qr[64];                        // mt0 fragments, filled at kv==0
    float acc[2][8][4];
#pragma unroll
    for (int mt = 0; mt < 2; mt++)
#pragma unroll
        for (int nt = 0; nt < 8; nt++)
#pragma unroll
            for (int j = 0; j < 4; j++) acc[mt][nt][j] = 0.f;
    float mrow[2][2] = {{-INFINITY, -INFINITY}, {-INFINITY, -INFINITY}};
    float lrow[2][2] = {{0.f, 0.f}, {0.f, 0.f}};

    for (int kv = 0; kv <= qb; kv++) {
        __syncthreads();  // (1) Ks(P)/Vs dead

        // stage K,V tile (64 x 128 each)
#pragma unroll
        for (int rnd = 0; rnd < 16; rnd++) {
            int row = row64 + rnd * 4;
            cp16(&Ks[row * AKS + c4], kB + (size_t)(kv * 64 + row) * H_DIM + c4);
            cp16(&Vs[row * AVS + c4], vB + (size_t)(kv * 64 + row) * H_DIM + c4);
        }
        CP_COMMIT;
        CP_WAIT0;

        if (kv == 0) {
            // one-time in-place rna rounding of Qs (same thread<->address map
            // as the staging, so no barrier needed before this point)
#pragma unroll
            for (int rnd = 0; rnd < 16; rnd++) {
                int row = row64 + rnd * 4;
                float4* p = (float4*)&Qs[row * 132 + c4];
                float4 vv = *p;
                vv.x = __uint_as_float(to_tf32(vv.x));
                vv.y = __uint_as_float(to_tf32(vv.y));
                vv.z = __uint_as_float(to_tf32(vv.z));
                vv.w = __uint_as_float(to_tf32(vv.w));
                *p = vv;
            }
        }
        __syncthreads();  // (2) tiles ready (+ rounded Qs on first iter)

        if (kv == 0) {
            // mt0 q fragments into registers from rounded Qs
            const int q0row = wm * 32 + lr;
#pragma unroll
            for (int ks = 0; ks < 16; ks++) {
                qr[ks * 4 + 0] = __float_as_uint(Qs[q0row * 132 + ks * 8 + lc]);
                qr[ks * 4 + 1] = __float_as_uint(Qs[(q0row + 8) * 132 + ks * 8 + lc]);
                qr[ks * 4 + 2] = __float_as_uint(Qs[q0row * 132 + ks * 8 + lc + 4]);
                qr[ks * 4 + 3] = __float_as_uint(Qs[(q0row + 8) * 132 + ks * 8 + lc + 4]);
            }
        }

        // ---- S = q @ k^T : rows 32*wm (2mt) x kv cols 32*wn (4nt), 1xTF32 ----
        float sc[2][4][4];
#pragma unroll
        for (int mt = 0; mt < 2; mt++)
#pragma unroll
            for (int nt = 0; nt < 4; nt++)
#pragma unroll
                for (int j = 0; j < 4; j++) sc[mt][nt][j] = 0.f;

        const int q1row = wm * 32 + 16 + lr;
#pragma unroll
        for (int ks = 0; ks < 16; ks++) {
            uint32_t q1[4];
            q1[0] = __float_as_uint(Qs[q1row * 132 + ks * 8 + lc]);
            q1[1] = __float_as_uint(Qs[(q1row + 8) * 132 + ks * 8 + lc]);
            q1[2] = __float_as_uint(Qs[q1row * 132 + ks * 8 + lc + 4]);
            q1[3] = __float_as_uint(Qs[(q1row + 8) * 132 + ks * 8 + lc + 4]);
#pragma unroll
            for (int nt = 0; nt < 4; nt++) {
                int kr = wn * 32 + nt * 8 + lr;
                uint32_t bh[2];
                bh[0] = __float_as_uint(Ks[kr * AKS + ks * 8 + lc]);
                bh[1] = __float_as_uint(Ks[kr * AKS + ks * 8 + lc + 4]);
                mma_tf32(sc[0][nt], &qr[ks * 4], bh);
                mma_tf32(sc[1][nt], q1, bh);
            }
        }

        // Diagonal-block causal mask (tile-local coords)
        if (kv == qb) {
#pragma unroll
            for (int mt = 0; mt < 2; mt++)
#pragma unroll
                for (int nt = 0; nt < 4; nt++)
#pragma unroll
                    for (int j = 0; j < 4; j++) {
                        int col = wn * 32 + nt * 8 + lc * 2 + (j & 1);
                        int row = wm * 32 + mt * 16 + lr + (j >> 1) * 8;
                        if (col > row) sc[mt][nt][j] = -INFINITY;
                    }
        }

        // ---- online softmax (exp2 domain, cross-warp over wn) ----
        float mnew[2][2] = {{-INFINITY, -INFINITY}, {-INFINITY, -INFINITY}};
#pragma unroll
        for (int mt = 0; mt < 2; mt++)
#pragma unroll
            for (int nt = 0; nt < 4; nt++)
#pragma unroll
                for (int j = 0; j < 4; j++)
                    mnew[mt][j >> 1] = fmaxf(mnew[mt][j >> 1], sc[mt][nt][j]);
#pragma unroll
        for (int off = 1; off < 4; off <<= 1)
#pragma unroll
            for (int mt = 0; mt < 2; mt++) {
                mnew[mt][0] = fmaxf(mnew[mt][0], __shfl_xor_sync(0xffffffffu, mnew[mt][0], off));
                mnew[mt][1] = fmaxf(mnew[mt][1], __shfl_xor_sync(0xffffffffu, mnew[mt][1], off));
            }
        if (lc == 0) {
#pragma unroll
            for (int mt = 0; mt < 2; mt++)
#pragma unroll
                for (int h = 0; h < 2; h++)
                    Xb[((wm * 2 + wn) * 4 + mt * 2 + h) * 8 + lr] = mnew[mt][h];
        }
        __syncthreads();  // (3) m-exchange

        float alpha[2][2];
#pragma unroll
        for (int mt = 0; mt < 2; mt++)
#pragma unroll
            for (int h = 0; h < 2; h++) {
                float mo = Xb[((wm * 2 + (1 - wn)) * 4 + mt * 2 + h) * 8 + lr];
                float mt_ = fmaxf(fmaxf(mrow[mt][h], mnew[mt][h]), mo);
                alpha[mt][h] = exp2f(mrow[mt][h] - mt_);
                mrow[mt][h] = mt_;
            }

        float rs[2][2] = {{0.f, 0.f}, {0.f, 0.f}};
#pragma unroll
        for (int mt = 0; mt < 2; mt++)
#pragma unroll
            for (int nt = 0; nt < 4; nt++)
#pragma unroll
                for (int j = 0; j < 4; j++) {
                    float p = exp2f(sc[mt][nt][j] - mrow[mt][j >> 1]);
                    sc[mt][nt][j] = p;
                    rs[mt][j >> 1] += p;
                }
#pragma unroll
        for (int off = 1; off < 4; off <<= 1)
#pragma unroll
            for (int mt = 0; mt < 2; mt++) {
                rs[mt][0] += __shfl_xor_sync(0xffffffffu, rs[mt][0], off);
                rs[mt][1] += __shfl_xor_sync(0xffffffffu, rs[mt][1], off);
            }

        // write P (rna) into dead Ks region; write rs partials
#pragma unroll
        for (int mt = 0; mt < 2; mt++)
#pragma unroll
            for (int nt = 0; nt < 4; nt++)
#pragma unroll
                for (int j = 0; j < 4; j++) {
                    int row = wm * 32 + mt * 16 + lr + (j >> 1) * 8;
                    int col = wn * 32 + nt * 8 + lc * 2 + (j & 1);
                    Ks[row * APS + col] = __uint_as_float(to_tf32(sc[mt][nt][j]));
                }
        if (lc == 0) {
#pragma unroll
            for (int mt = 0; mt < 2; mt++)
#pragma unroll
                for (int h = 0; h < 2; h++)
                    Xb[64 + ((wm * 2 + wn) * 4 + mt * 2 + h) * 8 + lr] = rs[mt][h];
        }
        __syncthreads();  // (4) P + rs ready

#pragma unroll
        for (int mt = 0; mt < 2; mt++)
#pragma unroll
            for (int h = 0; h < 2; h++) {
                float ro = Xb[64 + ((wm * 2 + (1 - wn)) * 4 + mt * 2 + h) * 8 + lr];
                lrow[mt][h] = lrow[mt][h] * alpha[mt][h] + rs[mt][h] + ro;
            }

#pragma unroll
        for (int mt = 0; mt < 2; mt++)
#pragma unroll
            for (int nt = 0; nt < 8; nt++) {
                acc[mt][nt][0] *= alpha[mt][0]; acc[mt][nt][1] *= alpha[mt][0];
                acc[mt][nt][2] *= alpha[mt][1]; acc[mt][nt][3] *= alpha[mt][1];
            }

        // ---- O += P @ V : rows 32*wm (2mt) x head cols 64*wn (8nt2), 1xTF32 ----
#pragma unroll
        for (int ks2 = 0; ks2 < 8; ks2++) {
            uint32_t pa[2][4];
#pragma unroll
            for (int mt = 0; mt < 2; mt++) {
                int base = wm * 32 + mt * 16;
                pa[mt][0] = __float_as_uint(Ks[(base + lr) * APS + ks2 * 8 + lc]);
                pa[mt][1] = __float_as_uint(Ks[(base + lr + 8) * APS + ks2 * 8 + lc]);
                pa[mt][2] = __float_as_uint(Ks[(base + lr) * APS + ks2 * 8 + lc + 4]);
                pa[mt][3] = __float_as_uint(Ks[(base + lr + 8) * APS + ks2 * 8 + lc + 4]);
            }
#pragma unroll
            for (int nt2 = 0; nt2 < 8; nt2++) {
                int vc = wn * 64 + nt2 * 8 + lr;
                uint32_t vb[2];
                vb[0] = __float_as_uint(Vs[(ks2 * 8 + lc) * AVS + vc]);
                vb[1] = __float_as_uint(Vs[(ks2 * 8 + lc + 4) * AVS + vc]);
                mma_tf32(acc[0][nt2], pa[0], vb);
                mma_tf32(acc[1][nt2], pa[1], vb);
            }
        }
    }

    // Epilogue
#pragma unroll
    for (int mt = 0; mt < 2; mt++) {
        float inv0 = 1.f / lrow[mt][0];
        float inv1 = 1.f / lrow[mt][1];
        size_t rowg = (size_t)b * S_LEN + qb * 64 + wm * 32 + mt * 16 + lr;
#pragma unroll
        for (int nt2 = 0; nt2 < 8; nt2++) {
            int col = wn * 64 + nt2 * 8 + lc * 2;
            *(float2*)(out + rowg * H_DIM + col) =
                make_float2(acc[mt][nt2][0] * inv0, acc[mt][nt2][1] * inv0);
            *(float2*)(out + (rowg + 8) * H_DIM + col) =
                make_float2(acc[mt][nt2][2] * inv1, acc[mt][nt2][3] * inv1);
        }
    }
}

// ---------------- launch ----------------

extern "C" void kernel_launch(void* const* d_in, const int* in_sizes, int n_in,
                              void* d_out, int out_size) {
    const float* x     = (const float*)d_in[0];
    const float* w_dkv = (const float*)d_in[1];
    const float* w_k   = (const float*)d_in[2];
    const float* w_v   = (const float*)d_in[3];
    const float* w_q   = (const float*)d_in[4];

    float* out = (float*)d_out;                          // [B,S,HEAD]
    float* latent = out + (size_t)M_TOTAL * H_DIM;       // [B,S,LATENT]

    float *qp, *kp, *vp, *wr;
    cudaGetSymbolAddress((void**)&qp, g_q);
    cudaGetSymbolAddress((void**)&kp, g_k);
    cudaGetSymbolAddress((void**)&vp, g_v);
    cudaGetSymbolAddress((void**)&wr, g_wr);

    static bool attrs_set = false;
    if (!attrs_set) {
        cudaFuncSetAttribute(gemm1_fused,
                             cudaFuncAttributeMaxDynamicSharedMemorySize, G_SMEM);
        cudaFuncSetAttribute(attn_kernel,
                             cudaFuncAttributeMaxDynamicSharedMemorySize, ATTN_SMEM_BYTES);
        attrs_set = true;
    }

    // 0) pre-round all weights to tf32-rna (unbiased)
    prep_w<<<WR_TOT / 256, 256>>>(w_dkv, w_q, w_k, w_v);

    // 1) fused: latent -> d_out; q -> scratch; k (scaled, rna), v (rna) -> scratch
    gemm1_fused<<<M_TOTAL / 64, 256, G_SMEM>>>(x, wr, latent, qp, kp, vp);

    // 2) causal flash attention (512 CTAs, 2/SM, longest-first)
    attn_kernel<<<512, 128, ATTN_SMEM_BYTES>>>(qp, kp, vp, out);
}

// round 15
// speedup vs baseline: 1.4244x; 1.0217x over previous
#include <cuda_runtime.h>
#include <cstdint>

#define M_TOTAL 32768
#define E_DIM 2048
#define L_DIM 64
#define H_DIM 128
#define S_LEN 4096

// Scratch (device globals: allocation-free rule)
__device__ float g_q[(size_t)M_TOTAL * H_DIM];
__device__ float g_k[(size_t)M_TOTAL * H_DIM];
__device__ float g_v[(size_t)M_TOTAL * H_DIM];

// Pre-rounded (tf32-rna) weights, same layouts as inputs:
#define WR_DKV 0
#define WR_Q   (2048 * 64)
#define WR_K   (WR_Q + 2048 * 128)
#define WR_V   (WR_K + 64 * 128)
#define WR_TOT (WR_V + 64 * 128)
__device__ float g_wr[WR_TOT];

// ---------------- tf32 / async helpers ----------------

__device__ __forceinline__ void mma_tf32(float* d, const uint32_t* a, const uint32_t* b) {
    asm volatile(
        "mma.sync.aligned.m16n8k8.row.col.f32.tf32.tf32.f32 "
        "{%0,%1,%2,%3}, {%4,%5,%6,%7}, {%8,%9}, {%0,%1,%2,%3};\n"
        : "+f"(d[0]), "+f"(d[1]), "+f"(d[2]), "+f"(d[3])
        : "r"(a[0]), "r"(a[1]), "r"(a[2]), "r"(a[3]), "r"(b[0]), "r"(b[1]));
}

__device__ __forceinline__ uint32_t to_tf32(float x) {
    uint32_t h;
    asm("cvt.rna.tf32.f32 %0, %1;" : "=r"(h) : "f"(x));
    return h;
}

__device__ __forceinline__ void cp16(void* dst, const void* src) {
    uint32_t d = (uint32_t)__cvta_generic_to_shared(dst);
    asm volatile("cp.async.cg.shared.global [%0], [%1], 16;\n" :: "r"(d), "l"(src));
}
#define CP_COMMIT asm volatile("cp.async.commit_group;\n")
#define CP_WAIT0  asm volatile("cp.async.wait_group 0;\n")
#define CP_WAIT1  asm volatile("cp.async.wait_group 1;\n")
#define CP_WAIT2  asm volatile("cp.async.wait_group 2;\n")

// k scale folded into the fused epilogue: 1/sqrt(128) * log2(e)
#define KSCALE_C (0.08838834764831845f * 1.4426950408889634f)

// ---------------- weight pre-rounding (once per call, ~5us) ----------------

__global__ void prep_w(const float* __restrict__ w_dkv, const float* __restrict__ w_q,
                       const float* __restrict__ w_k, const float* __restrict__ w_v) {
    int i = blockIdx.x * 256 + threadIdx.x;
    float v;
    if (i < WR_Q)       v = w_dkv[i];
    else if (i < WR_K)  v = w_q[i - WR_Q];
    else if (i < WR_V)  v = w_k[i - WR_K];
    else                v = w_v[i - WR_V];
    g_wr[i] = __uint_as_float(to_tf32(v));
}

// ---------------- fused GEMM1 + k/v decompress (R11, unchanged) ----------------

constexpr int G_BN = 192;
constexpr int G_KT = 32;
constexpr int G_ASTR = 36;
constexpr int G_BSTR = G_BN + 8;              // 200
constexpr int G_ASZ = 64 * G_ASTR;            // 2304
constexpr int G_BSZ = G_KT * G_BSTR;          // 6400
constexpr int G_BUF = G_ASZ + G_BSZ;          // 8704 floats
constexpr int G_SMEM = 3 * G_BUF * 4;         // 104448 bytes
constexpr int WSTR = 264;
constexpr int EP_WS = 0;
constexpr int EP_LS = 64 * WSTR;
constexpr int LSTR = 68;
static_assert(EP_LS + 64 * LSTR <= 3 * G_BUF, "epilogue overlay fits");

__global__ void __launch_bounds__(256, 2) gemm1_fused(
    const float* __restrict__ A,
    const float* __restrict__ wr,
    float* __restrict__ latent, float* __restrict__ qout,
    float* __restrict__ kout, float* __restrict__ vout)
{
    extern __shared__ float sh[];

    const int tid = threadIdx.x;
    const int warp = tid >> 5, lane = tid & 31;
    const int wm = warp >> 2;
    const int wn = warp & 3;
    const int lr = lane >> 2, lc = lane & 3;
    const int m0 = blockIdx.x * 64;

    const int arow = tid >> 2;
    const int ac4 = (tid & 3) * 4;

    const float* B1 = wr + WR_DKV;
    const float* B2 = wr + WR_Q;

    float acc[2][6][4];
#pragma unroll
    for (int mt = 0; mt < 2; mt++)
#pragma unroll
        for (int nt = 0; nt < 6; nt++)
#pragma unroll
            for (int j = 0; j < 4; j++) acc[mt][nt][j] = 0.f;

    const int nk = E_DIM / G_KT;

    auto stage = [&](int kt) {
        float* As = sh + (kt % 3) * G_BUF;
        float* Bs = As + G_ASZ;
        int kb = kt * G_KT;
        cp16(&As[arow * G_ASTR + ac4],      A + (size_t)(m0 + arow) * E_DIM + kb + ac4);
        cp16(&As[arow * G_ASTR + ac4 + 16], A + (size_t)(m0 + arow) * E_DIM + kb + ac4 + 16);
        constexpr int NB = (G_KT * G_BN / 4) / 256;  // 6
#pragma unroll
        for (int it = 0; it < NB; it++) {
            int i = it * 256 + tid;
            int brow = i / (G_BN / 4);
            int bc4 = (i % (G_BN / 4)) * 4;
            const float* src = (bc4 < 64) ? (B1 + (size_t)(kb + brow) * L_DIM + bc4)
                                          : (B2 + (size_t)(kb + brow) * H_DIM + (bc4 - 64));
            cp16(&Bs[brow * G_BSTR + bc4], src);
        }
        CP_COMMIT;
    };

    stage(0);
    stage(1);

    for (int kt = 0; kt < nk; kt++) {
        if (kt + 2 < nk) { stage(kt + 2); CP_WAIT2; }
        else if (kt + 1 < nk) CP_WAIT1;
        else CP_WAIT0;
        __syncthreads();

        const float* As = sh + (kt % 3) * G_BUF;
        const float* Bs = As + G_ASZ;

#pragma unroll
        for (int ks = 0; ks < 4; ks++) {
            uint32_t ah[2][4];
#pragma unroll
            for (int mt = 0; mt < 2; mt++) {
                int rb = wm * 32 + mt * 16;
                ah[mt][0] = to_tf32(As[(rb + lr) * G_ASTR + ks * 8 + lc]);
                ah[mt][1] = to_tf32(As[(rb + lr + 8) * G_ASTR + ks * 8 + lc]);
                ah[mt][2] = to_tf32(As[(rb + lr) * G_ASTR + ks * 8 + lc + 4]);
                ah[mt][3] = to_tf32(As[(rb + lr + 8) * G_ASTR + ks * 8 + lc + 4]);
            }
#pragma unroll
            for (int nt = 0; nt < 6; nt++) {
                int c0 = wn * 48 + nt * 8 + lr;
                uint32_t bh[2];
                bh[0] = __float_as_uint(Bs[(ks * 8 + lc) * G_BSTR + c0]);
                bh[1] = __float_as_uint(Bs[(ks * 8 + lc + 4) * G_BSTR + c0]);
#pragma unroll
                for (int mt = 0; mt < 2; mt++)
                    mma_tf32(acc[mt][nt], ah[mt], bh);
            }
        }
        __syncthreads();
    }

    // ---- epilogue: stage w_k|w_v into dead pipeline smem (overlapped) ----
    {
        float* Ws = sh + EP_WS;
#pragma unroll
        for (int it = 0; it < 16; it++) {
            int i = it * 256 + tid;
            int row = i >> 6;
            int c4 = (i & 63) * 4;
            const float* src = (c4 < 128) ? (wr + WR_K + (size_t)row * H_DIM + c4)
                                          : (wr + WR_V + (size_t)row * H_DIM + (c4 - 128));
            cp16(&Ws[row * WSTR + c4], src);
        }
        CP_COMMIT;
    }

    // ---- store latent (d_out + smem) and q (gmem) ----
    {
        float* Ls = sh + EP_LS;
#pragma unroll
        for (int mt = 0; mt < 2; mt++) {
            int rloc = wm * 32 + mt * 16 + lr;
            int r0 = m0 + rloc;
#pragma unroll
            for (int nt = 0; nt < 6; nt++) {
                int gc = wn * 48 + nt * 8 + lc * 2;
                float2 v01 = make_float2(acc[mt][nt][0], acc[mt][nt][1]);
                float2 v23 = make_float2(acc[mt][nt][2], acc[mt][nt][3]);
                if (gc < 64) {
                    *(float2*)(latent + (size_t)r0 * L_DIM + gc)       = v01;
                    *(float2*)(latent + (size_t)(r0 + 8) * L_DIM + gc) = v23;
                    *(float2*)&Ls[rloc * LSTR + gc]       = v01;
                    *(float2*)&Ls[(rloc + 8) * LSTR + gc] = v23;
                } else {
                    *(float2*)(qout + (size_t)r0 * H_DIM + gc - 64)       = v01;
                    *(float2*)(qout + (size_t)(r0 + 8) * H_DIM + gc - 64) = v23;
                }
            }
        }
    }
    CP_WAIT0;
    __syncthreads();

    // ---- k|v = latent @ [w_k|w_v] : warp = 32 rows (2mt) x 64 cols (8nt) ----
    {
        const float* Ws = sh + EP_WS;
        const float* Ls = sh + EP_LS;
        float acc2[2][8][4];
#pragma unroll
        for (int mt = 0; mt < 2; mt++)
#pragma unroll
            for (int nt = 0; nt < 8; nt++)
#pragma unroll
                for (int j = 0; j < 4; j++) acc2[mt][nt][j] = 0.f;

#pragma unroll
        for (int ks = 0; ks < 8; ks++) {
            uint32_t ah[2][4];
#pragma unroll
            for (int mt = 0; mt < 2; mt++) {
                int rb = wm * 32 + mt * 16;
                ah[mt][0] = to_tf32(Ls[(rb + lr) * LSTR + ks * 8 + lc]);
                ah[mt][1] = to_tf32(Ls[(rb + lr + 8) * LSTR + ks * 8 + lc]);
                ah[mt][2] = to_tf32(Ls[(rb + lr) * LSTR + ks * 8 + lc + 4]);
                ah[mt][3] = to_tf32(Ls[(rb + lr + 8) * LSTR + ks * 8 + lc + 4]);
            }
#pragma unroll
            for (int nt = 0; nt < 8; nt++) {
                int c0 = wn * 64 + nt * 8 + lr;
                uint32_t bh[2];
                bh[0] = __float_as_uint(Ws[(ks * 8 + lc) * WSTR + c0]);
                bh[1] = __float_as_uint(Ws[(ks * 8 + lc + 4) * WSTR + c0]);
#pragma unroll
                for (int mt = 0; mt < 2; mt++)
                    mma_tf32(acc2[mt][nt], ah[mt], bh);
            }
        }

#pragma unroll
        for (int mt = 0; mt < 2; mt++) {
            int r0 = m0 + wm * 32 + mt * 16 + lr;
#pragma unroll
            for (int nt = 0; nt < 8; nt++) {
                int gc = wn * 64 + nt * 8 + lc * 2;
                float* dst;
                int col;
                float cs;
                if (gc < 128) { dst = kout; col = gc;       cs = KSCALE_C; }
                else          { dst = vout; col = gc - 128; cs = 1.f; }
                float o0 = __uint_as_float(to_tf32(acc2[mt][nt][0] * cs));
                float o1 = __uint_as_float(to_tf32(acc2[mt][nt][1] * cs));
                float o2 = __uint_as_float(to_tf32(acc2[mt][nt][2] * cs));
                float o3 = __uint_as_float(to_tf32(acc2[mt][nt][3] * cs));
                *(float2*)(dst + (size_t)r0 * H_DIM + col)       = make_float2(o0, o1);
                *(float2*)(dst + (size_t)(r0 + 8) * H_DIM + col) = make_float2(o2, o3);
            }
        }
    }
}

// ---------------- Flash attention (causal), pipelined K/V prefetch ----------------
// R8 geometry: 4 warps x 16 rows each, every warp spans all 64 kv cols (QK) and
// all 128 head cols (PV) -> warp-local softmax, P in private smem (NOT aliasing K).
// Commit-group pipeline: K(t+1) issued after QK(t) (lands under softmax+PV(t));
// V(t+1) issued after PV(t) (lands under QK(t+1)). Both loads hidden.
// QK/PV 1xTF32; q rna in regs; k pre-scaled by 1/sqrt(128)*log2e; exp2 softmax.

constexpr int AKS = 132;
constexpr int AVS = 136;
constexpr int APS = 68;
constexpr int VOFF = 64 * AKS;              // 8448
constexpr int POFF = VOFF + 64 * AVS;       // 17152
constexpr int ATTN_SMEM_BYTES = (POFF + 64 * APS) * 4;   // 86016

__global__ void __launch_bounds__(128, 2) attn_kernel(
    const float* __restrict__ q, const float* __restrict__ k,
    const float* __restrict__ v, float* __restrict__ out)
{
    extern __shared__ float sm[];
    float* Ks = sm;
    float* Vs = sm + VOFF;
    float* Ps = sm + POFF;

    const int idx = blockIdx.x;
    const int b = idx & 7;
    const int qb = 63 - (idx >> 3);         // longest first
    const int tid = threadIdx.x;
    const int warp = tid >> 5, lane = tid & 31;
    const int lr = lane >> 2, lc = lane & 3;

    const float* qB = q + (size_t)b * S_LEN * H_DIM;
    const float* kB = k + (size_t)b * S_LEN * H_DIM;
    const float* vB = v + (size_t)b * S_LEN * H_DIM;

    const int qrow0 = qb * 64 + warp * 16 + lr;   // within-batch rows (and +8)

    const int row64 = tid >> 5;
    const int c4 = (tid & 31) * 4;

    auto loadK = [&](int t) {
#pragma unroll
        for (int rnd = 0; rnd < 16; rnd++) {
            int row = row64 + rnd * 4;
            cp16(&Ks[row * AKS + c4], kB + (size_t)(t * 64 + row) * H_DIM + c4);
        }
        CP_COMMIT;
    };
    auto loadV = [&](int t) {
#pragma unroll
        for (int rnd = 0; rnd < 16; rnd++) {
            int row = row64 + rnd * 4;
            cp16(&Vs[row * AVS + c4], vB + (size_t)(t * 64 + row) * H_DIM + c4);
        }
        CP_COMMIT;
    };

    // q fragments rna-rounded in registers (k carries the softmax scale)
    uint32_t qr[64];
#pragma unroll
    for (int ks = 0; ks < 16; ks++) {
        int c = ks * 8 + lc;
        qr[ks * 4 + 0] = to_tf32(qB[(size_t)qrow0 * H_DIM + c]);
        qr[ks * 4 + 1] = to_tf32(qB[(size_t)(qrow0 + 8) * H_DIM + c]);
        qr[ks * 4 + 2] = to_tf32(qB[(size_t)qrow0 * H_DIM + c + 4]);
        qr[ks * 4 + 3] = to_tf32(qB[(size_t)(qrow0 + 8) * H_DIM + c + 4]);
    }

    float acc[16][4];
#pragma unroll
    for (int nt = 0; nt < 16; nt++)
#pragma unroll
        for (int j = 0; j < 4; j++) acc[nt][j] = 0.f;
    float mrow[2] = {-INFINITY, -INFINITY};
    float lrow[2] = {0.f, 0.f};

    // prologue: stage K(0), V(0) as separate commit groups
    loadK(0);
    loadV(0);

    for (int kv = 0; kv <= qb; kv++) {
        // entry invariant: outstanding groups = [K(kv), V(kv)]
        CP_WAIT1;                 // K(kv) done; V(kv) may still be in flight
        __syncthreads();          // (A) Ks visible to all warps

        // ---- S = q @ k^T (1xTF32): 16 rows x 64 kv cols per warp ----
        float sc[8][4];
#pragma unroll
        for (int nt = 0; nt < 8; nt++)
#pragma unroll
            for (int j = 0; j < 4; j++) sc[nt][j] = 0.f;

#pragma unroll
        for (int ks = 0; ks < 16; ks++) {
#pragma unroll
            for (int nt = 0; nt < 8; nt++) {
                uint32_t bh[2];
                bh[0] = __float_as_uint(Ks[(nt * 8 + lr) * AKS + ks * 8 + lc]);
                bh[1] = __float_as_uint(Ks[(nt * 8 + lr) * AKS + ks * 8 + lc + 4]);
                mma_tf32(sc[nt], &qr[ks * 4], bh);
            }
        }
        __syncthreads();          // (B) all warps done reading Ks

        if (kv < qb) loadK(kv + 1);   // lands under softmax + PV

        // Diagonal-block causal mask
        if (kv == qb) {
#pragma unroll
            for (int nt = 0; nt < 8; nt++)
#pragma unroll
                for (int j = 0; j < 4; j++) {
                    int col = nt * 8 + lc * 2 + (j & 1);
                    int row = warp * 16 + lr + (j >> 1) * 8;
                    if (col > row) sc[nt][j] = -INFINITY;
                }
        }

        // ---- warp-local online softmax (exp2 domain) ----
        float mnew[2] = {-INFINITY, -INFINITY};
#pragma unroll
        for (int nt = 0; nt < 8; nt++)
#pragma unroll
            for (int j = 0; j < 4; j++) mnew[j >> 1] = fmaxf(mnew[j >> 1], sc[nt][j]);
#pragma unroll
        for (int off = 1; off < 4; off <<= 1) {
            mnew[0] = fmaxf(mnew[0], __shfl_xor_sync(0xffffffffu, mnew[0], off));
            mnew[1] = fmaxf(mnew[1], __shfl_xor_sync(0xffffffffu, mnew[1], off));
        }
        float mtot0 = fmaxf(mrow[0], mnew[0]);
        float mtot1 = fmaxf(mrow[1], mnew[1]);
        float alpha0 = exp2f(mrow[0] - mtot0);
        float alpha1 = exp2f(mrow[1] - mtot1);
        mrow[0] = mtot0; mrow[1] = mtot1;

        float rs[2] = {0.f, 0.f};
#pragma unroll
        for (int nt = 0; nt < 8; nt++)
#pragma unroll
            for (int j = 0; j < 4; j++) {
                float p = exp2f(sc[nt][j] - ((j >> 1) ? mtot1 : mtot0));
                sc[nt][j] = p;
                rs[j >> 1] += p;
            }
#pragma unroll
        for (int off = 1; off < 4; off <<= 1) {
            rs[0] += __shfl_xor_sync(0xffffffffu, rs[0], off);
            rs[1] += __shfl_xor_sync(0xffffffffu, rs[1], off);
        }
        lrow[0] = lrow[0] * alpha0 + rs[0];
        lrow[1] = lrow[1] * alpha1 + rs[1];

#pragma unroll
        for (int nt = 0; nt < 16; nt++) {
            acc[nt][0] *= alpha0; acc[nt][1] *= alpha0;
            acc[nt][2] *= alpha1; acc[nt][3] *= alpha1;
        }

        // P -> private smem (rna)
        float* Pw = Ps + warp * 16 * APS;
#pragma unroll
        for (int nt = 0; nt < 8; nt++)
#pragma unroll
            for (int j = 0; j < 4; j++) {
                int row = lr + (j >> 1) * 8;
                int col = nt * 8 + lc * 2 + (j & 1);
                Pw[row * APS + col] = __uint_as_float(to_tf32(sc[nt][j]));
            }
        __syncwarp();

        // V(kv) must be complete before PV.
        // outstanding: kv<qb -> [V(kv), K(kv+1)] : WAIT1 completes V(kv).
        //              kv==qb -> [V(kv)]        : WAIT0.
        if (kv < qb) CP_WAIT1; else CP_WAIT0;
        __syncthreads();          // (C) Vs visible to all warps

        // ---- O += P @ V (1xTF32): 16 rows x 128 head cols per warp ----
#pragma unroll
        for (int ks2 = 0; ks2 < 8; ks2++) {
            uint32_t pa[4];
            pa[0] = __float_as_uint(Pw[lr * APS + ks2 * 8 + lc]);
            pa[1] = __float_as_uint(Pw[(lr + 8) * APS + ks2 * 8 + lc]);
            pa[2] = __float_as_uint(Pw[lr * APS + ks2 * 8 + lc + 4]);
            pa[3] = __float_as_uint(Pw[(lr + 8) * APS + ks2 * 8 + lc + 4]);
#pragma unroll
            for (int nt2 = 0; nt2 < 16; nt2++) {
                uint32_t vb[2];
                vb[0] = __float_as_uint(Vs[(ks2 * 8 + lc) * AVS + nt2 * 8 + lr]);
                vb[1] = __float_as_uint(Vs[(ks2 * 8 + lc + 4) * AVS + nt2 * 8 + lr]);
                mma_tf32(acc[nt2], pa, vb);
            }
        }
        __syncthreads();          // (D) all warps done reading Vs

        if (kv < qb) loadV(kv + 1);   // lands under QK of next tile
    }

    // Epilogue
    float inv0 = 1.f / lrow[0];
    float inv1 = 1.f / lrow[1];
    size_t obase = ((size_t)b * S_LEN + qrow0) * H_DIM;
#pragma unroll
    for (int nt2 = 0; nt2 < 16; nt2++) {
        int col = nt2 * 8 + lc * 2;
        *(float2*)(out + obase + col) =
            make_float2(acc[nt2][0] * inv0, acc[nt2][1] * inv0);
        *(float2*)(out + obase + (size_t)8 * H_DIM + col) =
            make_float2(acc[nt2][2] * inv1, acc[nt2][3] * inv1);
    }
}

// ---------------- launch ----------------

extern "C" void kernel_launch(void* const* d_in, const int* in_sizes, int n_in,
                              void* d_out, int out_size) {
    const float* x     = (const float*)d_in[0];
    const float* w_dkv = (const float*)d_in[1];
    const float* w_k   = (const float*)d_in[2];
    const float* w_v   = (const float*)d_in[3];
    const float* w_q   = (const float*)d_in[4];

    float* out = (float*)d_out;                          // [B,S,HEAD]
    float* latent = out + (size_t)M_TOTAL * H_DIM;       // [B,S,LATENT]

    float *qp, *kp, *vp, *wr;
    cudaGetSymbolAddress((void**)&qp, g_q);
    cudaGetSymbolAddress((void**)&kp, g_k);
    cudaGetSymbolAddress((void**)&vp, g_v);
    cudaGetSymbolAddress((void**)&wr, g_wr);

    static bool attrs_set = false;
    if (!attrs_set) {
        cudaFuncSetAttribute(gemm1_fused,
                             cudaFuncAttributeMaxDynamicSharedMemorySize, G_SMEM);
        cudaFuncSetAttribute(attn_kernel,
                             cudaFuncAttributeMaxDynamicSharedMemorySize, ATTN_SMEM_BYTES);
        attrs_set = true;
    }

    // 0) pre-round all weights to tf32-rna (unbiased)
    prep_w<<<WR_TOT / 256, 256>>>(w_dkv, w_q, w_k, w_v);

    // 1) fused: latent -> d_out; q -> scratch; k (scaled, rna), v (rna) -> scratch
    gemm1_fused<<<M_TOTAL / 64, 256, G_SMEM>>>(x, wr, latent, qp, kp, vp);

    // 2) causal flash attention (512 CTAs, 2/SM, longest-first, K/V prefetch)
    attn_kernel<<<512, 128, ATTN_SMEM_BYTES>>>(qp, kp, vp, out);
}